// round 14
// baseline (speedup 1.0000x reference)
#include <cuda_runtime.h>
#include <cuda_fp16.h>
#include <cstdint>

#define M_ROWS 8192
#define EMB 1024
#define FFN 4096
#define NQ 32

// ---------------- scratch (device globals; no allocations) ----------------
__device__ __align__(16) __half g_attnv[M_ROWS * NQ];            // attention out (fp16)
__device__ __align__(16) __half g_combh[M_ROWS * EMB];           // combine out (fp16)
__device__ __align__(16) __half g_x1h  [M_ROWS * EMB];           // LN1 out (fp16)
__device__ __align__(16) __half g_qfh  [M_ROWS * NQ];            // ffn features (fp16)
__device__ __align__(16) __half g_ffnh [M_ROWS * EMB];           // ffn out (fp16)
__device__ __align__(16) __half g_wch  [EMB * NQ];
__device__ __align__(16) __half g_w1h  [FFN * NQ];
__device__ __align__(16) __half g_w2h  [(size_t)EMB * FFN];

// ---------------- helpers ----------------
__device__ __forceinline__ uint32_t smem_u32(const void* p) {
    uint32_t a;
    asm("{ .reg .u64 t; cvta.to.shared.u64 t, %1; cvt.u32.u64 %0, t; }" : "=r"(a) : "l"(p));
    return a;
}
__device__ __forceinline__ void cp16(uint32_t dst, const void* src) {
    asm volatile("cp.async.cg.shared.global [%0], [%1], 16;" :: "r"(dst), "l"(src));
}
__device__ __forceinline__ void cp_commit() { asm volatile("cp.async.commit_group;" ::: "memory"); }
template <int N> __device__ __forceinline__ void cp_wait() {
    asm volatile("cp.async.wait_group %0;" :: "n"(N) : "memory");
}
__device__ __forceinline__ void mma_fp16(float* c, const uint32_t* a, const uint32_t* b) {
    asm volatile(
        "mma.sync.aligned.m16n8k16.row.col.f32.f16.f16.f32 "
        "{%0,%1,%2,%3}, {%4,%5,%6,%7}, {%8,%9}, {%0,%1,%2,%3};"
        : "+f"(c[0]), "+f"(c[1]), "+f"(c[2]), "+f"(c[3])
        : "r"(a[0]), "r"(a[1]), "r"(a[2]), "r"(a[3]), "r"(b[0]), "r"(b[1]));
}
__device__ __forceinline__ void ldsm4(uint32_t* r, uint32_t addr) {
    asm volatile("ldmatrix.sync.aligned.m8n8.x4.shared.b16 {%0,%1,%2,%3}, [%4];"
                 : "=r"(r[0]), "=r"(r[1]), "=r"(r[2]), "=r"(r[3]) : "r"(addr));
}

static constexpr int SH = 40;            // smem row stride (halves) for k=32 tiles
static constexpr int SH2 = 72;           // smem row stride (halves) for k=64 tiles

// block-wide sum of (s, q) over 256 threads; result broadcast
__device__ __forceinline__ void blockReduce2(float& s, float& q) {
    __shared__ float buf[16];
    #pragma unroll
    for (int o = 16; o > 0; o >>= 1) {
        s += __shfl_xor_sync(0xffffffffu, s, o);
        q += __shfl_xor_sync(0xffffffffu, q, o);
    }
    int w = threadIdx.x >> 5, l = threadIdx.x & 31;
    if (l == 0) { buf[w] = s; buf[8 + w] = q; }
    __syncthreads();
    if (threadIdx.x < 32) {
        float ss = (l < 8) ? buf[l] : 0.0f;
        float qq = (l < 8) ? buf[8 + l] : 0.0f;
        #pragma unroll
        for (int o = 4; o > 0; o >>= 1) {
            ss += __shfl_xor_sync(0xffffffffu, ss, o);
            qq += __shfl_xor_sync(0xffffffffu, qq, o);
        }
        if (l == 0) { buf[0] = ss; buf[8] = qq; }
    }
    __syncthreads();
    s = buf[0];
    q = buf[8];
}

// ---------------- fp32 -> fp16 conversion ----------------
__global__ __launch_bounds__(256) void conv_fp16(const float* __restrict__ src,
                                                 __half* __restrict__ dst) {
    size_t i = (size_t)blockIdx.x * 256 + threadIdx.x;
    float4 v = ((const float4*)src)[i];
    __half2 h0 = __floats2half2_rn(v.x, v.y);
    __half2 h1 = __floats2half2_rn(v.z, v.w);
    ((uint2*)dst)[i] = make_uint2(*(uint32_t*)&h0, *(uint32_t*)&h1);
}

// ---------------- attention via separable Taylor features (R5/R11 version) ----------------
__global__ __launch_bounds__(256) void attn_kernel(const float* __restrict__ x,
                                                   const float* __restrict__ theta) {
    __shared__ float2 q2[1024];
    __shared__ float S[192];           // S0[64] | Sx[64] | Sy[64], idx [i*8+j]
    const float R = 0.84089641525371454f;   // 2^(-1/4)
    const float INVF[8]  = {1.f, 1.f, 0.5f, 1.f/6.f, 1.f/24.f, 1.f/120.f, 1.f/720.f, 1.f/5040.f};
    const float INVS[8]  = {1.f, 0.5f, 1.f/3.f, 0.25f, 0.2f, 1.f/6.f, 1.f/7.f, 0.125f};

    int bh = blockIdx.x;
    int b = bh >> 4, h = bh & 15;
    int tid = threadIdx.x;
    float c0 = cosf(theta[h * 2]);
    float c1 = cosf(theta[h * 2 + 1]);
    const float* xb = x + (size_t)b * 1024 * 1024 + h * 2;
    for (int i = tid; i < 1024; i += 256) {
        float2 v = *(const float2*)(xb + (size_t)i * 1024);
        q2[i] = make_float2(c0 * cosf(v.x), c1 * cosf(v.y));
    }
    __syncthreads();

    // phase 2: warp j accumulates features (i, j) for i=0..7
    {
        int j = tid >> 5, lane = tid & 31;
        float A0[8], Ax[8], Ay[8];
        #pragma unroll
        for (int i = 0; i < 8; i++) { A0[i] = 0.f; Ax[i] = 0.f; Ay[i] = 0.f; }
        for (int t = lane; t < 1024; t += 32) {
            float2 qt = q2[t];
            float utx = qt.x * R, uty = qt.y * R;
            float pty = INVF[j];
            for (int jj = 0; jj < j; jj++) pty *= uty;   // uniform per warp
            float p = pty;
            #pragma unroll
            for (int i = 0; i < 8; i++) {
                A0[i] += p;
                Ax[i] = fmaf(p, qt.x, Ax[i]);
                Ay[i] = fmaf(p, qt.y, Ay[i]);
                p *= utx * INVS[i];
            }
        }
        #pragma unroll
        for (int i = 0; i < 8; i++) {
            #pragma unroll
            for (int o = 16; o > 0; o >>= 1) {
                A0[i] += __shfl_xor_sync(0xffffffffu, A0[i], o);
                Ax[i] += __shfl_xor_sync(0xffffffffu, Ax[i], o);
                Ay[i] += __shfl_xor_sync(0xffffffffu, Ay[i], o);
            }
            if (lane == 0) {
                S[i * 8 + j]       = A0[i];
                S[64 + i * 8 + j]  = Ax[i];
                S[128 + i * 8 + j] = Ay[i];
            }
        }
    }
    __syncthreads();

    // phase 3: evaluate per s-row
    #pragma unroll
    for (int k = 0; k < 4; k++) {
        int s = k * 256 + tid;
        float2 qs = q2[s];
        float usx = qs.x * R, usy = qs.y * R;
        float psy[8];
        psy[0] = 1.f;
        #pragma unroll
        for (int j = 1; j < 8; j++) psy[j] = psy[j - 1] * usy;
        float d = 0.f, nx = 0.f, ny = 0.f, px = 1.f;
        #pragma unroll
        for (int i = 0; i < 8; i++) {
            float t0 = 0.f, t1 = 0.f, t2 = 0.f;
            #pragma unroll
            for (int j = 0; j < 8; j++) {
                float m = psy[j];
                t0 = fmaf(m, S[i * 8 + j], t0);
                t1 = fmaf(m, S[64 + i * 8 + j], t1);
                t2 = fmaf(m, S[128 + i * 8 + j], t2);
            }
            d  = fmaf(px, t0, d);
            nx = fmaf(px, t1, nx);
            ny = fmaf(px, t2, ny);
            px *= usx;
        }
        float inv = 1.0f / d;
        size_t o = ((size_t)b * 1024 + s) * NQ + h * 2;
        __half2 hv = __floats2half2_rn(nx * inv, ny * inv);
        *(uint32_t*)&g_attnv[o] = *(uint32_t*)&hv;
    }
}

// ---------------- combine GEMM (K=32): g_combh = g_attnv @ g_wch^T (fp16 out) ----------------
__global__ __launch_bounds__(256, 2) void combine_mma() {
    __shared__ __align__(16) __half As[128 * SH];
    __shared__ __align__(16) __half Bs[128 * SH];
    const int tid = threadIdx.x;
    const int wid = tid >> 5, lane = tid & 31;
    const int g = lane >> 2, t = lane & 3;
    const int wm = (wid >> 2) * 64, wn = (wid & 3) * 32;
    const int m0 = blockIdx.y * 128, n0 = blockIdx.x * 128;
    const __half* A = g_attnv + (size_t)m0 * NQ;
    const __half* B = g_wch + (size_t)n0 * NQ;

    uint32_t sa = smem_u32(As), sb = smem_u32(Bs);
    #pragma unroll
    for (int it = 0; it < 2; it++) {
        int idx = it * 256 + tid;
        int r = idx >> 2, u = idx & 3;
        cp16(sa + (uint32_t)(r * SH * 2 + u * 16), A + (size_t)r * NQ + u * 8);
        cp16(sb + (uint32_t)(r * SH * 2 + u * 16), B + (size_t)r * NQ + u * 8);
    }
    cp_commit();
    cp_wait<0>();
    __syncthreads();

    float c[16][4];
    #pragma unroll
    for (int i = 0; i < 16; i++)
        #pragma unroll
        for (int j = 0; j < 4; j++) c[i][j] = 0.0f;

    #pragma unroll
    for (int ks = 0; ks < 2; ks++) {
        int tk = ks * 16;
        uint32_t af[4][4], bf[4][2];
        #pragma unroll
        for (int mf = 0; mf < 4; mf++) {
            const __half* ap = As + (wm + mf * 16 + g) * SH + tk + 2 * t;
            af[mf][0] = *(const uint32_t*)(ap);
            af[mf][1] = *(const uint32_t*)(ap + 8 * SH);
            af[mf][2] = *(const uint32_t*)(ap + 8);
            af[mf][3] = *(const uint32_t*)(ap + 8 * SH + 8);
        }
        #pragma unroll
        for (int nf = 0; nf < 4; nf++) {
            const __half* bp = Bs + (wn + nf * 8 + g) * SH + tk + 2 * t;
            bf[nf][0] = *(const uint32_t*)(bp);
            bf[nf][1] = *(const uint32_t*)(bp + 8);
        }
        #pragma unroll
        for (int mf = 0; mf < 4; mf++)
            #pragma unroll
            for (int nf = 0; nf < 4; nf++)
                mma_fp16(c[mf * 4 + nf], af[mf], bf[nf]);
    }

    #pragma unroll
    for (int mf = 0; mf < 4; mf++) {
        int r0 = m0 + wm + mf * 16 + g;
        #pragma unroll
        for (int nf = 0; nf < 4; nf++) {
            int col = n0 + wn + nf * 8 + 2 * t;
            float* cf = c[mf * 4 + nf];
            __half2 h0 = __floats2half2_rn(cf[0], cf[1]);
            __half2 h1 = __floats2half2_rn(cf[2], cf[3]);
            *(uint32_t*)&g_combh[(size_t)r0 * EMB + col]       = *(uint32_t*)&h0;
            *(uint32_t*)&g_combh[(size_t)(r0 + 8) * EMB + col] = *(uint32_t*)&h1;
        }
    }
}

// ---------------- LN1 + qf (x1 stored fp16) ----------------
__global__ __launch_bounds__(256) void ln1_kernel(const float* __restrict__ x,
                                                  const float* __restrict__ g1,
                                                  const float* __restrict__ b1,
                                                  const float* __restrict__ thf) {
    int row = blockIdx.x;
    int tid = threadIdx.x;
    float4 xv = ((const float4*)(x + (size_t)row * EMB))[tid];
    uint2 cu = ((const uint2*)(g_combh + (size_t)row * EMB))[tid];
    float2 c01 = __half22float2(*(__half2*)&cu.x);
    float2 c23 = __half22float2(*(__half2*)&cu.y);
    float4 v = make_float4(xv.x + c01.x, xv.y + c01.y, xv.z + c23.x, xv.w + c23.y);
    float s = v.x + v.y + v.z + v.w;
    float q = v.x * v.x + v.y * v.y + v.z * v.z + v.w * v.w;
    blockReduce2(s, q);
    float mu = s * (1.0f / 1024.0f);
    float var = q * (1.0f / 1024.0f) - mu * mu;
    float rstd = rsqrtf(var + 1e-5f);
    float4 gv = ((const float4*)g1)[tid];
    float4 bv = ((const float4*)b1)[tid];
    float4 y = make_float4((v.x - mu) * rstd * gv.x + bv.x,
                           (v.y - mu) * rstd * gv.y + bv.y,
                           (v.z - mu) * rstd * gv.z + bv.z,
                           (v.w - mu) * rstd * gv.w + bv.w);
    __half2 y01 = __floats2half2_rn(y.x, y.y);
    __half2 y23 = __floats2half2_rn(y.z, y.w);
    ((uint2*)(g_x1h + (size_t)row * EMB))[tid] =
        make_uint2(*(uint32_t*)&y01, *(uint32_t*)&y23);
    if (tid < 8) {
        int e = tid * 4;
        __half2 h0 = __floats2half2_rn(cosf(thf[e + 0]) * cosf(y.x),
                                       cosf(thf[e + 1]) * cosf(y.y));
        __half2 h1 = __floats2half2_rn(cosf(thf[e + 2]) * cosf(y.z),
                                       cosf(thf[e + 3]) * cosf(y.w));
        *(uint2*)&g_qfh[(size_t)row * NQ + e] = make_uint2(*(uint32_t*)&h0, *(uint32_t*)&h1);
    }
}

// ---------------- fused FFN: CTA 128x128, 256 thr, 2 CTAs/SM, single h buffer ----------------
static constexpr int BK = 64;
static constexpr int NCH = FFN / BK;                  // 64
static constexpr int QF_B   = 128 * SH * 2;           // 10240
static constexpr int W1ST_B = 64 * SH * 2;            // 5120 per stage
static constexpr int W2ST_B = 128 * SH2 * 2;          // 18432 per stage
static constexpr int HB_B   = 128 * SH2 * 2;          // 18432 (single buffer)
static constexpr int OFF_W1 = QF_B;                   // 10240
static constexpr int OFF_W2 = OFF_W1 + 3 * W1ST_B;    // 25600
static constexpr int OFF_HB = OFF_W2 + 3 * W2ST_B;    // 80896
static constexpr int FG_SMEM = OFF_HB + HB_B;         // 99328 -> 2 CTAs/SM

__global__ __launch_bounds__(256, 2) void ffn_fused() {
    extern __shared__ __align__(16) __half smem[];
    const int tid = threadIdx.x;
    const int wid = tid >> 5, lane = tid & 31;
    const int g = lane >> 2, t = lane & 3;
    const int m0 = blockIdx.y * 128, n0 = blockIdx.x * 128;
    const uint32_t sbase = smem_u32(smem);
    const uint32_t sqf = sbase, shb = sbase + OFF_HB;

    const int lrA = lane & 15, lcA = (lane >> 4) * 8;
    const int lrB = (lane & 7) + ((lane >> 4) << 3), lcB = ((lane >> 3) & 1) * 8;

    // MMA1: 8 warps, warp tile 16(M) x 32(h-cols), 2 halves
    const int m1 = wid * 16;
    // MMA2: 2x4 grid, warp tile 64(M) x 32(N)
    const int wm2 = (wid & 1) * 64, wn2 = (wid >> 1) * 32;

    float c[16][4];
    #pragma unroll
    for (int i = 0; i < 16; i++)
        #pragma unroll
        for (int j = 0; j < 4; j++) c[i][j] = 0.0f;

    auto load_stage = [&](int ch, int stg) {
        uint32_t w1a = sbase + OFF_W1 + (uint32_t)stg * W1ST_B;
        {   // W1 chunk: 64 rows x 32 halves = 256 cp16
            int r = tid >> 2, u = tid & 3;
            cp16(w1a + (uint32_t)(r * SH * 2 + u * 16),
                 g_w1h + (size_t)(ch * BK + r) * NQ + u * 8);
        }
        uint32_t w2a = sbase + OFF_W2 + (uint32_t)stg * W2ST_B;
        const __half* bg = g_w2h + (size_t)n0 * FFN + ch * BK;
        #pragma unroll
        for (int it = 0; it < 4; it++) {   // W2 chunk: 128 rows x 64 halves = 1024 cp16
            int idx = it * 256 + tid;
            int r = idx >> 3, u = idx & 7;
            cp16(w2a + (uint32_t)(r * SH2 * 2 + u * 16), bg + (size_t)r * FFN + u * 8);
        }
        cp_commit();
    };

    // qf tile (128 x 32) + stages 0,1
    {
        const __half* A = g_qfh + (size_t)m0 * NQ;
        #pragma unroll
        for (int it = 0; it < 2; it++) {
            int idx = it * 256 + tid;
            int r = idx >> 2, u = idx & 3;
            cp16(sqf + (uint32_t)(r * SH * 2 + u * 16), A + (size_t)r * NQ + u * 8);
        }
        cp_commit();
        load_stage(0, 0);
        load_stage(1, 1);
    }

    for (int i = 0; i < NCH; i++) {
        if (i + 1 < NCH) cp_wait<1>();
        else             cp_wait<0>();
        __syncthreads();    // also orders prev MMA2 hb reads before this MMA1's writes
        int stg = i % 3;
        uint32_t w1a = sbase + OFF_W1 + (uint32_t)stg * W1ST_B;
        uint32_t w2a = sbase + OFF_W2 + (uint32_t)stg * W2ST_B;

        // ---- MMA1: h[128,64] = relu(qf @ W1chunk^T); warp tile 16 x 32, two halves
        #pragma unroll
        for (int kb = 0; kb < 2; kb++) {
            float c1[4][4];
            #pragma unroll
            for (int a = 0; a < 4; a++)
                #pragma unroll
                for (int bq = 0; bq < 4; bq++) c1[a][bq] = 0.0f;
            #pragma unroll
            for (int ks = 0; ks < 2; ks++) {
                int tk = ks * 16;
                uint32_t af[4], bf[4][2];
                ldsm4(af, sqf + (uint32_t)(((m1 + lrA) * SH + tk + lcA) * 2));
                #pragma unroll
                for (int nfp = 0; nfp < 2; nfp++) {
                    uint32_t tmp[4];
                    ldsm4(tmp, w1a + (uint32_t)(((kb * 32 + nfp * 16 + lrB) * SH + tk + lcB) * 2));
                    bf[2 * nfp][0] = tmp[0]; bf[2 * nfp][1] = tmp[1];
                    bf[2 * nfp + 1][0] = tmp[2]; bf[2 * nfp + 1][1] = tmp[3];
                }
                #pragma unroll
                for (int nf = 0; nf < 4; nf++)
                    mma_fp16(c1[nf], af, bf[nf]);
            }
            int r0 = m1 + g;
            #pragma unroll
            for (int nf = 0; nf < 4; nf++) {
                int col = kb * 32 + nf * 8 + 2 * t;
                __half2 h0 = __floats2half2_rn(fmaxf(c1[nf][0], 0.f), fmaxf(c1[nf][1], 0.f));
                __half2 h1 = __floats2half2_rn(fmaxf(c1[nf][2], 0.f), fmaxf(c1[nf][3], 0.f));
                asm volatile("st.shared.b32 [%0], %1;" ::
                    "r"(shb + (uint32_t)((r0 * SH2 + col) * 2)), "r"(*(uint32_t*)&h0) : "memory");
                asm volatile("st.shared.b32 [%0], %1;" ::
                    "r"(shb + (uint32_t)(((r0 + 8) * SH2 + col) * 2)), "r"(*(uint32_t*)&h1) : "memory");
            }
        }
        __syncthreads();

        // ---- MMA2: accumulate h @ W2chunk^T; warp tile 64x32
        #pragma unroll
        for (int ks = 0; ks < 4; ks++) {
            int tk = ks * 16;
            uint32_t af[4][4], bf[4][2];
            #pragma unroll
            for (int mf = 0; mf < 4; mf++)
                ldsm4(af[mf], shb + (uint32_t)(((wm2 + mf * 16 + lrA) * SH2 + tk + lcA) * 2));
            #pragma unroll
            for (int nfp = 0; nfp < 2; nfp++) {
                uint32_t tmp[4];
                ldsm4(tmp, w2a + (uint32_t)(((wn2 + nfp * 16 + lrB) * SH2 + tk + lcB) * 2));
                bf[2 * nfp][0] = tmp[0]; bf[2 * nfp][1] = tmp[1];
                bf[2 * nfp + 1][0] = tmp[2]; bf[2 * nfp + 1][1] = tmp[3];
            }
            #pragma unroll
            for (int mf = 0; mf < 4; mf++)
                #pragma unroll
                for (int nf = 0; nf < 4; nf++)
                    mma_fp16(c[mf * 4 + nf], af[mf], bf[nf]);
        }
        if (i + 2 < NCH) load_stage(i + 2, (i + 2) % 3);
    }

    #pragma unroll
    for (int mf = 0; mf < 4; mf++) {
        int r0 = m0 + wm2 + mf * 16 + g;
        #pragma unroll
        for (int nf = 0; nf < 4; nf++) {
            int col = n0 + wn2 + nf * 8 + 2 * t;
            float* cf = c[mf * 4 + nf];
            __half2 h0 = __floats2half2_rn(cf[0], cf[1]);
            __half2 h1 = __floats2half2_rn(cf[2], cf[3]);
            *(uint32_t*)&g_ffnh[(size_t)r0 * EMB + col]       = *(uint32_t*)&h0;
            *(uint32_t*)&g_ffnh[(size_t)(r0 + 8) * EMB + col] = *(uint32_t*)&h1;
        }
    }
}

// ---------------- LN2 -> out (x1 fp16) ----------------
__global__ __launch_bounds__(256) void ln2_kernel(const float* __restrict__ g2,
                                                  const float* __restrict__ b2,
                                                  float* __restrict__ out) {
    int row = blockIdx.x;
    int tid = threadIdx.x;
    uint2 xu = ((const uint2*)(g_x1h + (size_t)row * EMB))[tid];
    float2 x01 = __half22float2(*(__half2*)&xu.x);
    float2 x23 = __half22float2(*(__half2*)&xu.y);
    uint2 fu = ((const uint2*)(g_ffnh + (size_t)row * EMB))[tid];
    float2 f01 = __half22float2(*(__half2*)&fu.x);
    float2 f23 = __half22float2(*(__half2*)&fu.y);
    float4 v = make_float4(x01.x + f01.x, x01.y + f01.y, x23.x + f23.x, x23.y + f23.y);
    float s = v.x + v.y + v.z + v.w;
    float q = v.x * v.x + v.y * v.y + v.z * v.z + v.w * v.w;
    blockReduce2(s, q);
    float mu = s * (1.0f / 1024.0f);
    float var = q * (1.0f / 1024.0f) - mu * mu;
    float rstd = rsqrtf(var + 1e-5f);
    float4 gv = ((const float4*)g2)[tid];
    float4 bv = ((const float4*)b2)[tid];
    ((float4*)(out + (size_t)row * EMB))[tid] =
        make_float4((v.x - mu) * rstd * gv.x + bv.x,
                    (v.y - mu) * rstd * gv.y + bv.y,
                    (v.z - mu) * rstd * gv.z + bv.z,
                    (v.w - mu) * rstd * gv.w + bv.w);
}

// ---------------- launch ----------------
extern "C" void kernel_launch(void* const* d_in, const int* in_sizes, int n_in,
                              void* d_out, int out_size) {
    const float* x    = (const float*)d_in[0];
    const float* th_a = (const float*)d_in[1];
    const float* th_f = (const float*)d_in[2];
    const float* w_c  = (const float*)d_in[3];
    const float* w1   = (const float*)d_in[4];
    const float* w2   = (const float*)d_in[5];
    const float* g1   = (const float*)d_in[6];
    const float* b1   = (const float*)d_in[7];
    const float* g2   = (const float*)d_in[8];
    const float* b2   = (const float*)d_in[9];
    float* out = (float*)d_out;

    static cudaStream_t s2 = nullptr;
    static cudaEvent_t eF = nullptr, eJ = nullptr;
    if (!s2) {
        cudaFuncSetAttribute(ffn_fused, cudaFuncAttributeMaxDynamicSharedMemorySize, FG_SMEM);
        cudaStreamCreateWithFlags(&s2, cudaStreamNonBlocking);
        cudaEventCreateWithFlags(&eF, cudaEventDisableTiming);
        cudaEventCreateWithFlags(&eJ, cudaEventDisableTiming);
    }

    __half* wch; cudaGetSymbolAddress((void**)&wch, g_wch);
    __half* w1h; cudaGetSymbolAddress((void**)&w1h, g_w1h);
    __half* w2h; cudaGetSymbolAddress((void**)&w2h, g_w2h);

    // fork: w1/w2 conversions on s2, overlapping attn->combine->ln1 chain
    cudaEventRecord(eF, 0);
    cudaStreamWaitEvent(s2, eF, 0);
    conv_fp16<<<128, 256, 0, s2>>>(w1, w1h);
    conv_fp16<<<(EMB * FFN / 4) / 256, 256, 0, s2>>>(w2, w2h);
    cudaEventRecord(eJ, s2);

    conv_fp16<<<32, 256>>>(w_c, wch);
    attn_kernel<<<128, 256>>>(x, th_a);
    combine_mma<<<dim3(EMB / 128, M_ROWS / 128), 256>>>();
    ln1_kernel<<<M_ROWS, 256>>>(x, g1, b1, th_f);

    // join before ffn (needs w1h/w2h)
    cudaStreamWaitEvent(0, eJ, 0);
    ffn_fused<<<dim3(EMB / 128, M_ROWS / 128), 256, FG_SMEM>>>();
    ln2_kernel<<<M_ROWS, 256>>>(g2, b2, out);
}

// round 15
// speedup vs baseline: 1.1285x; 1.1285x over previous
#include <cuda_runtime.h>
#include <cuda_fp16.h>
#include <cstdint>

#define M_ROWS 8192
#define EMB 1024
#define FFN 4096
#define NQ 32

// ---------------- scratch (device globals; no allocations) ----------------
__device__ __align__(16) __half g_attnv[M_ROWS * NQ];            // attention out (fp16)
__device__ __align__(16) __half g_combh[M_ROWS * EMB];           // combine out (fp16)
__device__ __align__(16) __half g_x1h  [M_ROWS * EMB];           // LN1 out (fp16)
__device__ __align__(16) __half g_qfh  [M_ROWS * NQ];            // ffn features (fp16)
__device__ __align__(16) __half g_ffnh [M_ROWS * EMB];           // ffn out (fp16)
__device__ __align__(16) __half g_wch  [EMB * NQ];
__device__ __align__(16) __half g_w1h  [FFN * NQ];
__device__ __align__(16) __half g_w2h  [(size_t)EMB * FFN];

// ---------------- helpers ----------------
__device__ __forceinline__ uint32_t smem_u32(const void* p) {
    uint32_t a;
    asm("{ .reg .u64 t; cvta.to.shared.u64 t, %1; cvt.u32.u64 %0, t; }" : "=r"(a) : "l"(p));
    return a;
}
__device__ __forceinline__ void cp16(uint32_t dst, const void* src) {
    asm volatile("cp.async.cg.shared.global [%0], [%1], 16;" :: "r"(dst), "l"(src));
}
__device__ __forceinline__ void cp_commit() { asm volatile("cp.async.commit_group;" ::: "memory"); }
template <int N> __device__ __forceinline__ void cp_wait() {
    asm volatile("cp.async.wait_group %0;" :: "n"(N) : "memory");
}
__device__ __forceinline__ void mma_fp16(float* c, const uint32_t* a, const uint32_t* b) {
    asm volatile(
        "mma.sync.aligned.m16n8k16.row.col.f32.f16.f16.f32 "
        "{%0,%1,%2,%3}, {%4,%5,%6,%7}, {%8,%9}, {%0,%1,%2,%3};"
        : "+f"(c[0]), "+f"(c[1]), "+f"(c[2]), "+f"(c[3])
        : "r"(a[0]), "r"(a[1]), "r"(a[2]), "r"(a[3]), "r"(b[0]), "r"(b[1]));
}
__device__ __forceinline__ void ldsm4(uint32_t* r, uint32_t addr) {
    asm volatile("ldmatrix.sync.aligned.m8n8.x4.shared.b16 {%0,%1,%2,%3}, [%4];"
                 : "=r"(r[0]), "=r"(r[1]), "=r"(r[2]), "=r"(r[3]) : "r"(addr));
}

static constexpr int SH = 40;            // smem row stride (halves) for k=32 tiles
static constexpr int SH2 = 72;           // smem row stride (halves) for k=64 tiles

// block-wide sum of (s, q) over 256 threads; result broadcast
__device__ __forceinline__ void blockReduce2(float& s, float& q) {
    __shared__ float buf[16];
    #pragma unroll
    for (int o = 16; o > 0; o >>= 1) {
        s += __shfl_xor_sync(0xffffffffu, s, o);
        q += __shfl_xor_sync(0xffffffffu, q, o);
    }
    int w = threadIdx.x >> 5, l = threadIdx.x & 31;
    if (l == 0) { buf[w] = s; buf[8 + w] = q; }
    __syncthreads();
    if (threadIdx.x < 32) {
        float ss = (l < 8) ? buf[l] : 0.0f;
        float qq = (l < 8) ? buf[8 + l] : 0.0f;
        #pragma unroll
        for (int o = 4; o > 0; o >>= 1) {
            ss += __shfl_xor_sync(0xffffffffu, ss, o);
            qq += __shfl_xor_sync(0xffffffffu, qq, o);
        }
        if (l == 0) { buf[0] = ss; buf[8] = qq; }
    }
    __syncthreads();
    s = buf[0];
    q = buf[8];
}

// ---------------- fp32 -> fp16 conversion ----------------
__global__ __launch_bounds__(256) void conv_fp16(const float* __restrict__ src,
                                                 __half* __restrict__ dst) {
    size_t i = (size_t)blockIdx.x * 256 + threadIdx.x;
    float4 v = ((const float4*)src)[i];
    __half2 h0 = __floats2half2_rn(v.x, v.y);
    __half2 h1 = __floats2half2_rn(v.z, v.w);
    ((uint2*)dst)[i] = make_uint2(*(uint32_t*)&h0, *(uint32_t*)&h1);
}

// ---------------- attention via separable Taylor features (256 thr) ----------------
__global__ __launch_bounds__(256) void attn_kernel(const float* __restrict__ x,
                                                   const float* __restrict__ theta) {
    __shared__ float2 q2[1024];
    __shared__ float S[192];           // S0[64] | Sx[64] | Sy[64], idx [i*8+j]
    const float R = 0.84089641525371454f;   // 2^(-1/4)
    const float INVF[8]  = {1.f, 1.f, 0.5f, 1.f/6.f, 1.f/24.f, 1.f/120.f, 1.f/720.f, 1.f/5040.f};
    const float INVS[8]  = {1.f, 0.5f, 1.f/3.f, 0.25f, 0.2f, 1.f/6.f, 1.f/7.f, 0.125f};

    int bh = blockIdx.x;
    int b = bh >> 4, h = bh & 15;
    int tid = threadIdx.x;
    float c0 = cosf(theta[h * 2]);
    float c1 = cosf(theta[h * 2 + 1]);
    const float* xb = x + (size_t)b * 1024 * 1024 + h * 2;
    for (int i = tid; i < 1024; i += 256) {
        float2 v = *(const float2*)(xb + (size_t)i * 1024);
        q2[i] = make_float2(c0 * cosf(v.x), c1 * cosf(v.y));
    }
    __syncthreads();

    // phase 2: warp j accumulates features (i, j) for i=0..7
    {
        int j = tid >> 5, lane = tid & 31;
        float A0[8], Ax[8], Ay[8];
        #pragma unroll
        for (int i = 0; i < 8; i++) { A0[i] = 0.f; Ax[i] = 0.f; Ay[i] = 0.f; }
        for (int t = lane; t < 1024; t += 32) {
            float2 qt = q2[t];
            float utx = qt.x * R, uty = qt.y * R;
            float pty = INVF[j];
            for (int jj = 0; jj < j; jj++) pty *= uty;   // uniform per warp
            float p = pty;
            #pragma unroll
            for (int i = 0; i < 8; i++) {
                A0[i] += p;
                Ax[i] = fmaf(p, qt.x, Ax[i]);
                Ay[i] = fmaf(p, qt.y, Ay[i]);
                p *= utx * INVS[i];
            }
        }
        #pragma unroll
        for (int i = 0; i < 8; i++) {
            #pragma unroll
            for (int o = 16; o > 0; o >>= 1) {
                A0[i] += __shfl_xor_sync(0xffffffffu, A0[i], o);
                Ax[i] += __shfl_xor_sync(0xffffffffu, Ax[i], o);
                Ay[i] += __shfl_xor_sync(0xffffffffu, Ay[i], o);
            }
            if (lane == 0) {
                S[i * 8 + j]       = A0[i];
                S[64 + i * 8 + j]  = Ax[i];
                S[128 + i * 8 + j] = Ay[i];
            }
        }
    }
    __syncthreads();

    // phase 3: evaluate per s-row
    #pragma unroll
    for (int k = 0; k < 4; k++) {
        int s = k * 256 + tid;
        float2 qs = q2[s];
        float usx = qs.x * R, usy = qs.y * R;
        float psy[8];
        psy[0] = 1.f;
        #pragma unroll
        for (int j = 1; j < 8; j++) psy[j] = psy[j - 1] * usy;
        float d = 0.f, nx = 0.f, ny = 0.f, px = 1.f;
        #pragma unroll
        for (int i = 0; i < 8; i++) {
            float t0 = 0.f, t1 = 0.f, t2 = 0.f;
            #pragma unroll
            for (int j = 0; j < 8; j++) {
                float m = psy[j];
                t0 = fmaf(m, S[i * 8 + j], t0);
                t1 = fmaf(m, S[64 + i * 8 + j], t1);
                t2 = fmaf(m, S[128 + i * 8 + j], t2);
            }
            d  = fmaf(px, t0, d);
            nx = fmaf(px, t1, nx);
            ny = fmaf(px, t2, ny);
            px *= usx;
        }
        float inv = 1.0f / d;
        size_t o = ((size_t)b * 1024 + s) * NQ + h * 2;
        __half2 hv = __floats2half2_rn(nx * inv, ny * inv);
        *(uint32_t*)&g_attnv[o] = *(uint32_t*)&hv;
    }
}

// ---------------- combine GEMM (K=32): g_combh = g_attnv @ g_wch^T (fp16 out) ----------------
__global__ __launch_bounds__(256, 2) void combine_mma() {
    __shared__ __align__(16) __half As[128 * SH];
    __shared__ __align__(16) __half Bs[128 * SH];
    const int tid = threadIdx.x;
    const int wid = tid >> 5, lane = tid & 31;
    const int g = lane >> 2, t = lane & 3;
    const int wm = (wid >> 2) * 64, wn = (wid & 3) * 32;
    const int m0 = blockIdx.y * 128, n0 = blockIdx.x * 128;
    const __half* A = g_attnv + (size_t)m0 * NQ;
    const __half* B = g_wch + (size_t)n0 * NQ;

    uint32_t sa = smem_u32(As), sb = smem_u32(Bs);
    #pragma unroll
    for (int it = 0; it < 2; it++) {
        int idx = it * 256 + tid;
        int r = idx >> 2, u = idx & 3;
        cp16(sa + (uint32_t)(r * SH * 2 + u * 16), A + (size_t)r * NQ + u * 8);
        cp16(sb + (uint32_t)(r * SH * 2 + u * 16), B + (size_t)r * NQ + u * 8);
    }
    cp_commit();
    cp_wait<0>();
    __syncthreads();

    float c[16][4];
    #pragma unroll
    for (int i = 0; i < 16; i++)
        #pragma unroll
        for (int j = 0; j < 4; j++) c[i][j] = 0.0f;

    #pragma unroll
    for (int ks = 0; ks < 2; ks++) {
        int tk = ks * 16;
        uint32_t af[4][4], bf[4][2];
        #pragma unroll
        for (int mf = 0; mf < 4; mf++) {
            const __half* ap = As + (wm + mf * 16 + g) * SH + tk + 2 * t;
            af[mf][0] = *(const uint32_t*)(ap);
            af[mf][1] = *(const uint32_t*)(ap + 8 * SH);
            af[mf][2] = *(const uint32_t*)(ap + 8);
            af[mf][3] = *(const uint32_t*)(ap + 8 * SH + 8);
        }
        #pragma unroll
        for (int nf = 0; nf < 4; nf++) {
            const __half* bp = Bs + (wn + nf * 8 + g) * SH + tk + 2 * t;
            bf[nf][0] = *(const uint32_t*)(bp);
            bf[nf][1] = *(const uint32_t*)(bp + 8);
        }
        #pragma unroll
        for (int mf = 0; mf < 4; mf++)
            #pragma unroll
            for (int nf = 0; nf < 4; nf++)
                mma_fp16(c[mf * 4 + nf], af[mf], bf[nf]);
    }

    #pragma unroll
    for (int mf = 0; mf < 4; mf++) {
        int r0 = m0 + wm + mf * 16 + g;
        #pragma unroll
        for (int nf = 0; nf < 4; nf++) {
            int col = n0 + wn + nf * 8 + 2 * t;
            float* cf = c[mf * 4 + nf];
            __half2 h0 = __floats2half2_rn(cf[0], cf[1]);
            __half2 h1 = __floats2half2_rn(cf[2], cf[3]);
            *(uint32_t*)&g_combh[(size_t)r0 * EMB + col]       = *(uint32_t*)&h0;
            *(uint32_t*)&g_combh[(size_t)(r0 + 8) * EMB + col] = *(uint32_t*)&h1;
        }
    }
}

// ---------------- LN1 + qf (x1 stored fp16) ----------------
__global__ __launch_bounds__(256) void ln1_kernel(const float* __restrict__ x,
                                                  const float* __restrict__ g1,
                                                  const float* __restrict__ b1,
                                                  const float* __restrict__ thf) {
    int row = blockIdx.x;
    int tid = threadIdx.x;
    float4 xv = ((const float4*)(x + (size_t)row * EMB))[tid];
    uint2 cu = ((const uint2*)(g_combh + (size_t)row * EMB))[tid];
    float2 c01 = __half22float2(*(__half2*)&cu.x);
    float2 c23 = __half22float2(*(__half2*)&cu.y);
    float4 v = make_float4(xv.x + c01.x, xv.y + c01.y, xv.z + c23.x, xv.w + c23.y);
    float s = v.x + v.y + v.z + v.w;
    float q = v.x * v.x + v.y * v.y + v.z * v.z + v.w * v.w;
    blockReduce2(s, q);
    float mu = s * (1.0f / 1024.0f);
    float var = q * (1.0f / 1024.0f) - mu * mu;
    float rstd = rsqrtf(var + 1e-5f);
    float4 gv = ((const float4*)g1)[tid];
    float4 bv = ((const float4*)b1)[tid];
    float4 y = make_float4((v.x - mu) * rstd * gv.x + bv.x,
                           (v.y - mu) * rstd * gv.y + bv.y,
                           (v.z - mu) * rstd * gv.z + bv.z,
                           (v.w - mu) * rstd * gv.w + bv.w);
    __half2 y01 = __floats2half2_rn(y.x, y.y);
    __half2 y23 = __floats2half2_rn(y.z, y.w);
    ((uint2*)(g_x1h + (size_t)row * EMB))[tid] =
        make_uint2(*(uint32_t*)&y01, *(uint32_t*)&y23);
    if (tid < 8) {
        int e = tid * 4;
        __half2 h0 = __floats2half2_rn(cosf(thf[e + 0]) * cosf(y.x),
                                       cosf(thf[e + 1]) * cosf(y.y));
        __half2 h1 = __floats2half2_rn(cosf(thf[e + 2]) * cosf(y.z),
                                       cosf(thf[e + 3]) * cosf(y.w));
        *(uint2*)&g_qfh[(size_t)row * NQ + e] = make_uint2(*(uint32_t*)&h0, *(uint32_t*)&h1);
    }
}

// ---------------- fused FFN (R9/R11 structure): g_ffnh = relu(qf@W1^T) @ W2^T ----------------
static constexpr int BK = 64;
static constexpr int NCH = FFN / BK;                  // 64
static constexpr int QF_B   = 128 * SH * 2;           // 10240
static constexpr int W1ST_B = 64 * SH * 2;            // 5120 per stage
static constexpr int W2ST_B = 256 * SH2 * 2;          // 36864 per stage
static constexpr int HB_B   = 128 * SH2 * 2;          // 18432 per buffer
static constexpr int OFF_W1 = QF_B;                   // 10240
static constexpr int OFF_W2 = OFF_W1 + 3 * W1ST_B;    // 25600
static constexpr int OFF_HB = OFF_W2 + 3 * W2ST_B;    // 136192
static constexpr int FG_SMEM = OFF_HB + 2 * HB_B;     // 173056

__global__ __launch_bounds__(512, 1) void ffn_fused() {
    extern __shared__ __align__(16) __half smem[];
    const int tid = threadIdx.x;
    const int wid = tid >> 5, lane = tid & 31;
    const int g = lane >> 2, t = lane & 3;
    const int m0 = blockIdx.y * 128, n0 = blockIdx.x * 256;
    const uint32_t sbase = smem_u32(smem);
    const uint32_t sqf = sbase, shb = sbase + OFF_HB;

    const int lrA = lane & 15, lcA = (lane >> 4) * 8;
    const int lrB = (lane & 7) + ((lane >> 4) << 3), lcB = ((lane >> 3) & 1) * 8;

    // MMA1 warp mapping: 16 warps, warp tile 16(M) x 32(N of h)
    const int m1 = (wid & 7) * 16, n1 = (wid >> 3) * 32;
    // MMA2 warp mapping: 4x4 grid, warp tile 32(M) x 64(N)
    const int wm2 = (wid & 3) * 32, wn2 = (wid >> 2) * 64;

    float c[16][4];
    #pragma unroll
    for (int i = 0; i < 16; i++)
        #pragma unroll
        for (int j = 0; j < 4; j++) c[i][j] = 0.0f;

    auto load_stage = [&](int ch, int stg) {
        uint32_t w1a = sbase + OFF_W1 + (uint32_t)stg * W1ST_B;
        if (tid < 256) {   // W1 chunk: 64 rows x 32 halves = 256 cp16
            int r = tid >> 2, u = tid & 3;
            cp16(w1a + (uint32_t)(r * SH * 2 + u * 16),
                 g_w1h + (size_t)(ch * BK + r) * NQ + u * 8);
        }
        uint32_t w2a = sbase + OFF_W2 + (uint32_t)stg * W2ST_B;
        const __half* bg = g_w2h + (size_t)n0 * FFN + ch * BK;
        #pragma unroll
        for (int it = 0; it < 4; it++) {   // W2 chunk: 256 rows x 64 halves = 2048 cp16
            int idx = it * 512 + tid;
            int r = idx >> 3, u = idx & 7;
            cp16(w2a + (uint32_t)(r * SH2 * 2 + u * 16), bg + (size_t)r * FFN + u * 8);
        }
        cp_commit();
    };

    // qf tile (128 x 32) + stages 0,1
    {
        const __half* A = g_qfh + (size_t)m0 * NQ;
        int r = tid >> 2, u = tid & 3;        // 512 cp16 exactly
        cp16(sqf + (uint32_t)(r * SH * 2 + u * 16), A + (size_t)r * NQ + u * 8);
        cp_commit();
        load_stage(0, 0);
        load_stage(1, 1);
    }

    uint32_t qfa[2][4];                       // persistent qf A-fragments (loaded at i==0)

    for (int i = 0; i < NCH; i++) {
        if (i + 1 < NCH) cp_wait<1>();
        else             cp_wait<0>();
        __syncthreads();
        int stg = i % 3;
        uint32_t w1a = sbase + OFF_W1 + (uint32_t)stg * W1ST_B;
        uint32_t w2a = sbase + OFF_W2 + (uint32_t)stg * W2ST_B;
        uint32_t hb  = shb + (uint32_t)(i & 1) * HB_B;

        // ---- MMA1: h[128,64] = relu(qf @ W1chunk^T); warp tile 16x32
        {
            if (i == 0) {
                #pragma unroll
                for (int ks = 0; ks < 2; ks++)
                    ldsm4(qfa[ks], sqf + (uint32_t)(((m1 + lrA) * SH + ks * 16 + lcA) * 2));
            }
            float c1[4][4];
            #pragma unroll
            for (int a = 0; a < 4; a++)
                #pragma unroll
                for (int bq = 0; bq < 4; bq++) c1[a][bq] = 0.0f;
            #pragma unroll
            for (int ks = 0; ks < 2; ks++) {
                int tk = ks * 16;
                uint32_t bf[4][2];
                #pragma unroll
                for (int nfp = 0; nfp < 2; nfp++) {
                    uint32_t tmp[4];
                    ldsm4(tmp, w1a + (uint32_t)(((n1 + nfp * 16 + lrB) * SH + tk + lcB) * 2));
                    bf[2 * nfp][0] = tmp[0]; bf[2 * nfp][1] = tmp[1];
                    bf[2 * nfp + 1][0] = tmp[2]; bf[2 * nfp + 1][1] = tmp[3];
                }
                #pragma unroll
                for (int nf = 0; nf < 4; nf++)
                    mma_fp16(c1[nf], qfa[ks], bf[nf]);
            }
            int r0 = m1 + g;
            #pragma unroll
            for (int nf = 0; nf < 4; nf++) {
                int col = n1 + nf * 8 + 2 * t;
                __half2 h0 = __floats2half2_rn(fmaxf(c1[nf][0], 0.f), fmaxf(c1[nf][1], 0.f));
                __half2 h1 = __floats2half2_rn(fmaxf(c1[nf][2], 0.f), fmaxf(c1[nf][3], 0.f));
                asm volatile("st.shared.b32 [%0], %1;" ::
                    "r"(hb + (uint32_t)((r0 * SH2 + col) * 2)), "r"(*(uint32_t*)&h0) : "memory");
                asm volatile("st.shared.b32 [%0], %1;" ::
                    "r"(hb + (uint32_t)(((r0 + 8) * SH2 + col) * 2)), "r"(*(uint32_t*)&h1) : "memory");
            }
        }
        __syncthreads();

        // ---- MMA2: accumulate h @ W2chunk^T; warp tile 32x64
        #pragma unroll
        for (int ks = 0; ks < 4; ks++) {
            int tk = ks * 16;
            uint32_t af[2][4], bf[8][2];
            #pragma unroll
            for (int mf = 0; mf < 2; mf++)
                ldsm4(af[mf], hb + (uint32_t)(((wm2 + mf * 16 + lrA) * SH2 + tk + lcA) * 2));
            #pragma unroll
            for (int nfp = 0; nfp < 4; nfp++) {
                uint32_t tmp[4];
                ldsm4(tmp, w2a + (uint32_t)(((wn2 + nfp * 16 + lrB) * SH2 + tk + lcB) * 2));
                bf[2 * nfp][0] = tmp[0]; bf[2 * nfp][1] = tmp[1];
                bf[2 * nfp + 1][0] = tmp[2]; bf[2 * nfp + 1][1] = tmp[3];
            }
            #pragma unroll
            for (int mf = 0; mf < 2; mf++)
                #pragma unroll
                for (int nf = 0; nf < 8; nf++)
                    mma_fp16(c[mf * 8 + nf], af[mf], bf[nf]);
        }
        if (i + 2 < NCH) load_stage(i + 2, (i + 2) % 3);
    }

    #pragma unroll
    for (int mf = 0; mf < 2; mf++) {
        int r0 = m0 + wm2 + mf * 16 + g;
        #pragma unroll
        for (int nf = 0; nf < 8; nf++) {
            int col = n0 + wn2 + nf * 8 + 2 * t;
            float* cf = c[mf * 8 + nf];
            __half2 h0 = __floats2half2_rn(cf[0], cf[1]);
            __half2 h1 = __floats2half2_rn(cf[2], cf[3]);
            *(uint32_t*)&g_ffnh[(size_t)r0 * EMB + col]       = *(uint32_t*)&h0;
            *(uint32_t*)&g_ffnh[(size_t)(r0 + 8) * EMB + col] = *(uint32_t*)&h1;
        }
    }
}

// ---------------- LN2 -> out (x1 fp16) ----------------
__global__ __launch_bounds__(256) void ln2_kernel(const float* __restrict__ g2,
                                                  const float* __restrict__ b2,
                                                  float* __restrict__ out) {
    int row = blockIdx.x;
    int tid = threadIdx.x;
    uint2 xu = ((const uint2*)(g_x1h + (size_t)row * EMB))[tid];
    float2 x01 = __half22float2(*(__half2*)&xu.x);
    float2 x23 = __half22float2(*(__half2*)&xu.y);
    uint2 fu = ((const uint2*)(g_ffnh + (size_t)row * EMB))[tid];
    float2 f01 = __half22float2(*(__half2*)&fu.x);
    float2 f23 = __half22float2(*(__half2*)&fu.y);
    float4 v = make_float4(x01.x + f01.x, x01.y + f01.y, x23.x + f23.x, x23.y + f23.y);
    float s = v.x + v.y + v.z + v.w;
    float q = v.x * v.x + v.y * v.y + v.z * v.z + v.w * v.w;
    blockReduce2(s, q);
    float mu = s * (1.0f / 1024.0f);
    float var = q * (1.0f / 1024.0f) - mu * mu;
    float rstd = rsqrtf(var + 1e-5f);
    float4 gv = ((const float4*)g2)[tid];
    float4 bv = ((const float4*)b2)[tid];
    ((float4*)(out + (size_t)row * EMB))[tid] =
        make_float4((v.x - mu) * rstd * gv.x + bv.x,
                    (v.y - mu) * rstd * gv.y + bv.y,
                    (v.z - mu) * rstd * gv.z + bv.z,
                    (v.w - mu) * rstd * gv.w + bv.w);
}

// ---------------- launch ----------------
extern "C" void kernel_launch(void* const* d_in, const int* in_sizes, int n_in,
                              void* d_out, int out_size) {
    const float* x    = (const float*)d_in[0];
    const float* th_a = (const float*)d_in[1];
    const float* th_f = (const float*)d_in[2];
    const float* w_c  = (const float*)d_in[3];
    const float* w1   = (const float*)d_in[4];
    const float* w2   = (const float*)d_in[5];
    const float* g1   = (const float*)d_in[6];
    const float* b1   = (const float*)d_in[7];
    const float* g2   = (const float*)d_in[8];
    const float* b2   = (const float*)d_in[9];
    float* out = (float*)d_out;

    static cudaStream_t s2 = nullptr;
    static cudaEvent_t eF = nullptr, eJ = nullptr;
    if (!s2) {
        cudaFuncSetAttribute(ffn_fused, cudaFuncAttributeMaxDynamicSharedMemorySize, FG_SMEM);
        cudaStreamCreateWithFlags(&s2, cudaStreamNonBlocking);
        cudaEventCreateWithFlags(&eF, cudaEventDisableTiming);
        cudaEventCreateWithFlags(&eJ, cudaEventDisableTiming);
    }

    __half* wch; cudaGetSymbolAddress((void**)&wch, g_wch);
    __half* w1h; cudaGetSymbolAddress((void**)&w1h, g_w1h);
    __half* w2h; cudaGetSymbolAddress((void**)&w2h, g_w2h);

    // fork: w1/w2 conversions on s2, overlapping attn->combine->ln1 chain
    cudaEventRecord(eF, 0);
    cudaStreamWaitEvent(s2, eF, 0);
    conv_fp16<<<128, 256, 0, s2>>>(w1, w1h);
    conv_fp16<<<(EMB * FFN / 4) / 256, 256, 0, s2>>>(w2, w2h);
    cudaEventRecord(eJ, s2);

    conv_fp16<<<32, 256>>>(w_c, wch);
    attn_kernel<<<128, 256>>>(x, th_a);
    combine_mma<<<dim3(EMB / 128, M_ROWS / 128), 256>>>();
    ln1_kernel<<<M_ROWS, 256>>>(x, g1, b1, th_f);

    // join before ffn (needs w1h/w2h)
    cudaStreamWaitEvent(0, eJ, 0);
    ffn_fused<<<dim3(EMB / 256, M_ROWS / 128), 512, FG_SMEM>>>();
    ln2_kernel<<<M_ROWS, 256>>>(g2, b2, out);
}